// round 1
// baseline (speedup 1.0000x reference)
#include <cuda_runtime.h>
#include <cuda_bf16.h>
#include <math.h>

// Problem constants
#define NNODES 200000
#define NEDGES 3200000
#define BN_EPS 1e-5f

// ---------------------------------------------------------------------------
// Static device scratch (allocation-free contract: __device__ globals)
// ---------------------------------------------------------------------------
__device__ float g_buf0[(size_t)NNODES * 256];   // 205 MB
__device__ float g_buf1[(size_t)NNODES * 256];   // 205 MB
__device__ float g_buf2[(size_t)NNODES * 40];    // 32 MB  (final agg out)

__device__ int   g_cnt[NNODES];
__device__ int   g_cur[NNODES];
__device__ int   g_rowptr[NNODES + 1];
__device__ float g_dinv[NNODES];
__device__ int   g_colidx[NEDGES];
__device__ float g_w[NEDGES];

__device__ double g_sum[256];
__device__ double g_sumsq[256];
__device__ float  g_scale[256];
__device__ float  g_shift[256];

// ---------------------------------------------------------------------------
// CSR build
// ---------------------------------------------------------------------------
__global__ void zero_counts_kernel() {
    int i = blockIdx.x * blockDim.x + threadIdx.x;
    if (i < NNODES) { g_cnt[i] = 0; g_cur[i] = 0; }
}

__global__ void count_kernel(const int* __restrict__ row) {
    int e = blockIdx.x * blockDim.x + threadIdx.x;
    if (e < NEDGES) atomicAdd(&g_cnt[row[e]], 1);
}

__global__ void dinv_kernel() {
    int i = blockIdx.x * blockDim.x + threadIdx.x;
    if (i < NNODES) {
        float deg = (float)(g_cnt[i] + 1);   // +1 self loop, always >= 1
        g_dinv[i] = rsqrtf(deg);
    }
}

// Single-block exclusive scan over g_cnt -> g_rowptr
__global__ void scan_kernel() {
    __shared__ int partial[1024];
    const int t = threadIdx.x;
    const int CH = (NNODES + 1023) / 1024;
    int start = t * CH;
    int end = start + CH; if (end > NNODES) end = NNODES;
    int s = 0;
    for (int i = start; i < end; i++) s += g_cnt[i];
    partial[t] = s;
    __syncthreads();
    // Hillis-Steele inclusive scan
    for (int o = 1; o < 1024; o <<= 1) {
        int v = (t >= o) ? partial[t - o] : 0;
        __syncthreads();
        partial[t] += v;
        __syncthreads();
    }
    int base = (t == 0) ? 0 : partial[t - 1];
    for (int i = start; i < end; i++) {
        g_rowptr[i] = base;
        base += g_cnt[i];
    }
    if (t == 1023) g_rowptr[NNODES] = base;
}

__global__ void fill_kernel(const int* __restrict__ row, const int* __restrict__ col) {
    int e = blockIdx.x * blockDim.x + threadIdx.x;
    if (e >= NEDGES) return;
    int d = row[e];
    int s = col[e];
    int p = g_rowptr[d] + atomicAdd(&g_cur[d], 1);
    g_colidx[p] = s;
    g_w[p] = g_dinv[d] * g_dinv[s];
}

// ---------------------------------------------------------------------------
// Pull-based aggregation: out[i] = dinv[i]^2 * h[i] + sum_e w[e]*h[col[e]]
// ---------------------------------------------------------------------------
template <int F, int NPB>
__global__ void agg_kernel(const float* __restrict__ h, float* __restrict__ out) {
    int local = threadIdx.x / F;
    int f = threadIdx.x % F;
    int node = blockIdx.x * NPB + local;
    if (node >= NNODES) return;

    int start = g_rowptr[node];
    int end = g_rowptr[node + 1];
    float di = g_dinv[node];
    float acc0 = di * di * h[(size_t)node * F + f];
    float acc1 = 0.f, acc2 = 0.f, acc3 = 0.f;

    int e = start;
    for (; e + 4 <= end; e += 4) {
        int c0 = g_colidx[e + 0], c1 = g_colidx[e + 1];
        int c2 = g_colidx[e + 2], c3 = g_colidx[e + 3];
        float w0 = g_w[e + 0], w1 = g_w[e + 1];
        float w2 = g_w[e + 2], w3 = g_w[e + 3];
        acc0 += w0 * h[(size_t)c0 * F + f];
        acc1 += w1 * h[(size_t)c1 * F + f];
        acc2 += w2 * h[(size_t)c2 * F + f];
        acc3 += w3 * h[(size_t)c3 * F + f];
    }
    for (; e < end; e++)
        acc0 += g_w[e] * h[(size_t)g_colidx[e] * F + f];

    out[(size_t)node * F + f] = (acc0 + acc1) + (acc2 + acc3);
}

// ---------------------------------------------------------------------------
// SGEMM: C[Nrows,M] = A[Nrows,K] @ B[K,M], fp32 smem-tiled
// ---------------------------------------------------------------------------
template <int BM, int BN, int BK, int TM, int TN>
__global__ void sgemm_kernel(int Nrows, int K, int M,
                             const float* __restrict__ A,
                             const float* __restrict__ B,
                             float* __restrict__ C) {
    constexpr int THREADS = (BM / TM) * (BN / TN);
    __shared__ float As[BK][BM];
    __shared__ float Bs[BK][BN];

    const int tid = threadIdx.x;
    const int brow = blockIdx.x * BM;
    const int bcol = blockIdx.y * BN;
    const int tcol = (tid % (BN / TN)) * TN;
    const int trow = (tid / (BN / TN)) * TM;

    constexpr int AK4 = BK / 4;
    const int aRow0 = tid / AK4;
    const int aCol = (tid % AK4) * 4;
    constexpr int ASTRIDE = THREADS / AK4;

    constexpr int BNV = BN / 4;
    const int bRow0 = tid / BNV;
    const int bCol = (tid % BNV) * 4;
    constexpr int BSTRIDE = THREADS / BNV;

    float acc[TM][TN] = {};

    for (int k0 = 0; k0 < K; k0 += BK) {
        #pragma unroll
        for (int r = aRow0; r < BM; r += ASTRIDE) {
            int g = brow + r;
            float4 v = make_float4(0.f, 0.f, 0.f, 0.f);
            if (g < Nrows)
                v = *reinterpret_cast<const float4*>(A + (size_t)g * K + k0 + aCol);
            As[aCol + 0][r] = v.x;
            As[aCol + 1][r] = v.y;
            As[aCol + 2][r] = v.z;
            As[aCol + 3][r] = v.w;
        }
        #pragma unroll
        for (int r = bRow0; r < BK; r += BSTRIDE) {
            int gc = bcol + bCol;
            float4 v = make_float4(0.f, 0.f, 0.f, 0.f);
            if (gc < M)
                v = *reinterpret_cast<const float4*>(B + (size_t)(k0 + r) * M + gc);
            *reinterpret_cast<float4*>(&Bs[r][bCol]) = v;
        }
        __syncthreads();

        #pragma unroll
        for (int k = 0; k < BK; k++) {
            float ra[TM], rb[TN];
            #pragma unroll
            for (int i = 0; i < TM; i++) ra[i] = As[k][trow + i];
            #pragma unroll
            for (int j = 0; j < TN; j++) rb[j] = Bs[k][tcol + j];
            #pragma unroll
            for (int i = 0; i < TM; i++)
                #pragma unroll
                for (int j = 0; j < TN; j++)
                    acc[i][j] += ra[i] * rb[j];
        }
        __syncthreads();
    }

    #pragma unroll
    for (int i = 0; i < TM; i++) {
        int g = brow + trow + i;
        if (g >= Nrows) continue;
        #pragma unroll
        for (int j = 0; j < TN; j += 4) {
            int gc = bcol + tcol + j;
            if (gc < M) {
                float4 v = make_float4(acc[i][j], acc[i][j + 1], acc[i][j + 2], acc[i][j + 3]);
                *reinterpret_cast<float4*>(C + (size_t)g * M + gc) = v;
            }
        }
    }
}

// ---------------------------------------------------------------------------
// BatchNorm (over axis 0) + ReLU
// ---------------------------------------------------------------------------
__global__ void bn_zero_kernel() {
    int f = threadIdx.x;
    g_sum[f] = 0.0;
    g_sumsq[f] = 0.0;
}

__global__ void bn_stats_kernel(const float* __restrict__ h) {
    const int ROWS = 512;
    int f = threadIdx.x;  // 256 threads, one per feature
    int r0 = blockIdx.x * ROWS;
    int r1 = r0 + ROWS; if (r1 > NNODES) r1 = NNODES;
    float s = 0.f, s2 = 0.f;
    for (int r = r0; r < r1; r++) {
        float v = h[(size_t)r * 256 + f];
        s += v;
        s2 += v * v;
    }
    atomicAdd(&g_sum[f], (double)s);
    atomicAdd(&g_sumsq[f], (double)s2);
}

__global__ void bn_finalize_kernel(const float* __restrict__ gamma,
                                   const float* __restrict__ beta) {
    int f = threadIdx.x;
    double mu = g_sum[f] / (double)NNODES;
    double var = g_sumsq[f] / (double)NNODES - mu * mu;
    float sc = gamma[f] * rsqrtf((float)var + BN_EPS);
    g_scale[f] = sc;
    g_shift[f] = beta[f] - (float)mu * sc;
}

__global__ void bn_apply_relu_kernel(float* __restrict__ h) {
    size_t idx = (size_t)blockIdx.x * blockDim.x + threadIdx.x;  // float4 index
    size_t total4 = (size_t)NNODES * 64;
    if (idx >= total4) return;
    int col4 = (int)(idx & 63) * 4;
    float4 v = *reinterpret_cast<float4*>(h + idx * 4);
    v.x = fmaxf(v.x * g_scale[col4 + 0] + g_shift[col4 + 0], 0.f);
    v.y = fmaxf(v.y * g_scale[col4 + 1] + g_shift[col4 + 1], 0.f);
    v.z = fmaxf(v.z * g_scale[col4 + 2] + g_shift[col4 + 2], 0.f);
    v.w = fmaxf(v.w * g_scale[col4 + 3] + g_shift[col4 + 3], 0.f);
    *reinterpret_cast<float4*>(h + idx * 4) = v;
}

// ---------------------------------------------------------------------------
// log_softmax over 40 classes (one warp per node), fused +b3
// ---------------------------------------------------------------------------
__global__ void logsoftmax_kernel(const float* __restrict__ in,
                                  const float* __restrict__ b3,
                                  float* __restrict__ out) {
    int warp = (blockIdx.x * blockDim.x + threadIdx.x) >> 5;
    int lane = threadIdx.x & 31;
    if (warp >= NNODES) return;
    const float* r = in + (size_t)warp * 40;
    float v0 = r[lane] + b3[lane];
    bool has2 = (lane + 32) < 40;
    float v1 = has2 ? (r[lane + 32] + b3[lane + 32]) : -INFINITY;

    float m = fmaxf(v0, v1);
    #pragma unroll
    for (int o = 16; o > 0; o >>= 1) m = fmaxf(m, __shfl_xor_sync(0xFFFFFFFFu, m, o));

    float s = expf(v0 - m) + (has2 ? expf(v1 - m) : 0.f);
    #pragma unroll
    for (int o = 16; o > 0; o >>= 1) s += __shfl_xor_sync(0xFFFFFFFFu, s, o);

    float lse = m + logf(s);
    out[(size_t)warp * 40 + lane] = v0 - lse;
    if (has2) out[(size_t)warp * 40 + lane + 32] = v1 - lse;
}

// ---------------------------------------------------------------------------
// Launch
// ---------------------------------------------------------------------------
extern "C" void kernel_launch(void* const* d_in, const int* in_sizes, int n_in,
                              void* d_out, int out_size) {
    const float* x      = (const float*)d_in[0];
    const int*   ei     = (const int*)d_in[1];     // [2, E]
    const float* W1     = (const float*)d_in[2];
    // b1 (d_in[3]) cancels in batchnorm exactly
    const float* gamma1 = (const float*)d_in[4];
    const float* beta1  = (const float*)d_in[5];
    const float* W2     = (const float*)d_in[6];
    // b2 (d_in[7]) cancels in batchnorm exactly
    const float* gamma2 = (const float*)d_in[8];
    const float* beta2  = (const float*)d_in[9];
    const float* W3     = (const float*)d_in[10];
    const float* b3     = (const float*)d_in[11];
    float* out = (float*)d_out;

    const int* row = ei;
    const int* col = ei + NEDGES;

    float *buf0, *buf1, *buf2;
    cudaGetSymbolAddress((void**)&buf0, g_buf0);
    cudaGetSymbolAddress((void**)&buf1, g_buf1);
    cudaGetSymbolAddress((void**)&buf2, g_buf2);

    const int EB = (NEDGES + 255) / 256;
    const int NB = (NNODES + 255) / 256;

    // ---- CSR build (once) ----
    zero_counts_kernel<<<NB, 256>>>();
    count_kernel<<<EB, 256>>>(row);
    dinv_kernel<<<NB, 256>>>();
    scan_kernel<<<1, 1024>>>();
    fill_kernel<<<EB, 256>>>(row, col);

    // ---- Layer 1: agg(x, F=128) -> GEMM 128->256 -> BN+ReLU ----
    agg_kernel<128, 2><<<(NNODES + 1) / 2, 256>>>(x, buf0);
    {
        dim3 grid((NNODES + 127) / 128, 2);
        sgemm_kernel<128, 128, 16, 8, 8><<<grid, 256>>>(NNODES, 128, 256, buf0, W1, buf1);
    }
    bn_zero_kernel<<<1, 256>>>();
    bn_stats_kernel<<<(NNODES + 511) / 512, 256>>>(buf1);
    bn_finalize_kernel<<<1, 256>>>(gamma1, beta1);
    bn_apply_relu_kernel<<<(int)(((size_t)NNODES * 64 + 255) / 256), 256>>>(buf1);

    // ---- Layer 2: agg(h1, F=256) -> GEMM 256->256 -> BN+ReLU ----
    agg_kernel<256, 1><<<NNODES, 256>>>(buf1, buf0);
    {
        dim3 grid((NNODES + 127) / 128, 2);
        sgemm_kernel<128, 128, 16, 8, 8><<<grid, 256>>>(NNODES, 256, 256, buf0, W2, buf1);
    }
    bn_zero_kernel<<<1, 256>>>();
    bn_stats_kernel<<<(NNODES + 511) / 512, 256>>>(buf1);
    bn_finalize_kernel<<<1, 256>>>(gamma2, beta2);
    bn_apply_relu_kernel<<<(int)(((size_t)NNODES * 64 + 255) / 256), 256>>>(buf1);

    // ---- Layer 3: GEMM 256->40 -> agg(F=40) -> +b3, log_softmax ----
    {
        dim3 grid((NNODES + 127) / 128, 1);
        sgemm_kernel<128, 64, 16, 8, 4><<<grid, 256>>>(NNODES, 256, 40, buf1, W3, buf0);
    }
    agg_kernel<40, 6><<<(NNODES + 5) / 6, 240>>>(buf0, buf2);
    logsoftmax_kernel<<<(NNODES + 7) / 8, 256>>>(buf2, b3, out);
}

// round 2
// speedup vs baseline: 1.8512x; 1.8512x over previous
#include <cuda_runtime.h>
#include <cuda_bf16.h>
#include <math.h>
#include <stdint.h>

#define NNODES 200000
#define NEDGES 3200000
#define BN_EPS 1e-5f
#define SCAN_BLOCKS ((NNODES + 1023) / 1024)   // 196

// ---------------------------------------------------------------------------
// Static device scratch
// ---------------------------------------------------------------------------
__device__ float g_buf0[(size_t)NNODES * 256];
__device__ float g_buf1[(size_t)NNODES * 256];
__device__ float g_buf2[(size_t)NNODES * 40];

__device__ int   g_cnt[NNODES];
__device__ int   g_cur[NNODES];
__device__ int   g_rowptr[NNODES + 1];
__device__ float g_dinv[NNODES];
__device__ int   g_colidx[NEDGES];
__device__ float g_w[NEDGES];

__device__ int   g_bsum[256];
__device__ int   g_boff[256];

__device__ double g_sum[256];
__device__ double g_sumsq[256];
__device__ float  g_scale[256];
__device__ float  g_shift[256];

// ---------------------------------------------------------------------------
// Small helpers
// ---------------------------------------------------------------------------
__device__ __forceinline__ uint32_t f2tf(float f) {
    uint32_t u;
    asm("cvt.rna.tf32.f32 %0, %1;" : "=r"(u) : "f"(f));
    return u;
}

__device__ __forceinline__ void mma_tf32(float* c, const uint32_t* a, const uint32_t* b) {
    asm volatile(
        "mma.sync.aligned.m16n8k8.row.col.f32.tf32.tf32.f32 "
        "{%0,%1,%2,%3}, {%4,%5,%6,%7}, {%8,%9}, {%0,%1,%2,%3};\n"
        : "+f"(c[0]), "+f"(c[1]), "+f"(c[2]), "+f"(c[3])
        : "r"(a[0]), "r"(a[1]), "r"(a[2]), "r"(a[3]), "r"(b[0]), "r"(b[1]));
}

__device__ __forceinline__ int warp_incl_scan(int v) {
    #pragma unroll
    for (int o = 1; o < 32; o <<= 1) {
        int n = __shfl_up_sync(0xFFFFFFFFu, v, o);
        if ((threadIdx.x & 31) >= o) v += n;
    }
    return v;
}

// ---------------------------------------------------------------------------
// CSR build
// ---------------------------------------------------------------------------
__global__ void zero_counts_kernel() {
    int i = blockIdx.x * blockDim.x + threadIdx.x;
    if (i < NNODES) { g_cnt[i] = 0; g_cur[i] = 0; }
}

__global__ void count_kernel(const int* __restrict__ row) {
    int e = blockIdx.x * blockDim.x + threadIdx.x;
    if (e < NEDGES) atomicAdd(&g_cnt[row[e]], 1);
}

__global__ void dinv_kernel() {
    int i = blockIdx.x * blockDim.x + threadIdx.x;
    if (i < NNODES) {
        float deg = (float)(g_cnt[i] + 1);
        g_dinv[i] = rsqrtf(deg);
    }
}

// Stage 1: per-block (1024 elems) sums
__global__ __launch_bounds__(1024) void scan_block_sums_kernel() {
    __shared__ int sm[32];
    int i = blockIdx.x * 1024 + threadIdx.x;
    int v = (i < NNODES) ? g_cnt[i] : 0;
    #pragma unroll
    for (int o = 16; o > 0; o >>= 1) v += __shfl_down_sync(0xFFFFFFFFu, v, o);
    if ((threadIdx.x & 31) == 0) sm[threadIdx.x >> 5] = v;
    __syncthreads();
    if (threadIdx.x < 32) {
        int s = sm[threadIdx.x];
        #pragma unroll
        for (int o = 16; o > 0; o >>= 1) s += __shfl_down_sync(0xFFFFFFFFu, s, o);
        if (threadIdx.x == 0) g_bsum[blockIdx.x] = s;
    }
}

// Stage 2: exclusive scan of block sums (196 values, one block of 256)
__global__ void scan_bsums_kernel() {
    __shared__ int wsum[8];
    int t = threadIdx.x;
    int v = (t < SCAN_BLOCKS) ? g_bsum[t] : 0;
    int incl = warp_incl_scan(v);
    if ((t & 31) == 31) wsum[t >> 5] = incl;
    __syncthreads();
    if (t < 8) {
        int s = wsum[t];
        #pragma unroll
        for (int o = 1; o < 8; o <<= 1) {
            int n = __shfl_up_sync(0xFFu, s, o);
            if (t >= o) s += n;
        }
        wsum[t] = s;
    }
    __syncthreads();
    int warp = t >> 5;
    if (warp > 0) incl += wsum[warp - 1];
    g_boff[t] = incl - v;   // exclusive
}

// Stage 3: block-local inclusive scan + offset -> rowptr
__global__ __launch_bounds__(1024) void scan_write_kernel() {
    __shared__ int wsum[32];
    int i = blockIdx.x * 1024 + threadIdx.x;
    int v = (i < NNODES) ? g_cnt[i] : 0;
    int incl = warp_incl_scan(v);
    int lane = threadIdx.x & 31;
    int warp = threadIdx.x >> 5;
    if (lane == 31) wsum[warp] = incl;
    __syncthreads();
    if (threadIdx.x < 32) wsum[threadIdx.x] = warp_incl_scan(wsum[threadIdx.x]);
    __syncthreads();
    if (warp > 0) incl += wsum[warp - 1];
    if (i < NNODES) g_rowptr[i] = g_boff[blockIdx.x] + incl - v;
    if (i == 0) g_rowptr[NNODES] = NEDGES;
}

__global__ void fill_kernel(const int* __restrict__ row, const int* __restrict__ col) {
    int e = blockIdx.x * blockDim.x + threadIdx.x;
    if (e >= NEDGES) return;
    int d = row[e];
    int s = col[e];
    int p = g_rowptr[d] + atomicAdd(&g_cur[d], 1);
    g_colidx[p] = s;
    g_w[p] = g_dinv[d] * g_dinv[s];
}

// ---------------------------------------------------------------------------
// Vectorized pull aggregation (float4 lanes), optional fused BN+ReLU on input.
//   out[i] = w_self * T(h[i]) + sum_e w[e] * T(h[col[e]])
//   T(v) = BN ? relu(v*scale+shift) : v
// s4 = row stride in float4, c4off = feature offset in float4 units
// ---------------------------------------------------------------------------
template <int F4, int NPB, bool BN>
__global__ __launch_bounds__(F4 * NPB) void agg_vec_kernel(
    const float4* __restrict__ h, float4* __restrict__ out, int s4, int c4off)
{
    int local = threadIdx.x / F4;
    int f4 = threadIdx.x % F4;
    int node = blockIdx.x * NPB + local;
    if (node >= NNODES) return;

    float4 sc, sh;
    if (BN) {
        sc = *((const float4*)g_scale + c4off + f4);
        sh = *((const float4*)g_shift + c4off + f4);
    }

    auto T = [&](float4 v) -> float4 {
        if (BN) {
            v.x = fmaxf(fmaf(v.x, sc.x, sh.x), 0.f);
            v.y = fmaxf(fmaf(v.y, sc.y, sh.y), 0.f);
            v.z = fmaxf(fmaf(v.z, sc.z, sh.z), 0.f);
            v.w = fmaxf(fmaf(v.w, sc.w, sh.w), 0.f);
        }
        return v;
    };

    int start = g_rowptr[node];
    int end = g_rowptr[node + 1];
    float di = g_dinv[node];
    float ws = di * di;

    float4 v = T(h[(size_t)node * s4 + c4off + f4]);
    float4 a0 = make_float4(v.x * ws, v.y * ws, v.z * ws, v.w * ws);
    float4 a1 = make_float4(0, 0, 0, 0), a2 = a1, a3 = a1;

    int e = start;
    for (; e + 4 <= end; e += 4) {
        int c0 = g_colidx[e + 0], c1 = g_colidx[e + 1];
        int c2 = g_colidx[e + 2], c3 = g_colidx[e + 3];
        float w0 = g_w[e + 0], w1 = g_w[e + 1], w2 = g_w[e + 2], w3 = g_w[e + 3];
        float4 v0 = T(h[(size_t)c0 * s4 + c4off + f4]);
        float4 v1 = T(h[(size_t)c1 * s4 + c4off + f4]);
        float4 v2 = T(h[(size_t)c2 * s4 + c4off + f4]);
        float4 v3 = T(h[(size_t)c3 * s4 + c4off + f4]);
        a0.x = fmaf(v0.x, w0, a0.x); a0.y = fmaf(v0.y, w0, a0.y);
        a0.z = fmaf(v0.z, w0, a0.z); a0.w = fmaf(v0.w, w0, a0.w);
        a1.x = fmaf(v1.x, w1, a1.x); a1.y = fmaf(v1.y, w1, a1.y);
        a1.z = fmaf(v1.z, w1, a1.z); a1.w = fmaf(v1.w, w1, a1.w);
        a2.x = fmaf(v2.x, w2, a2.x); a2.y = fmaf(v2.y, w2, a2.y);
        a2.z = fmaf(v2.z, w2, a2.z); a2.w = fmaf(v2.w, w2, a2.w);
        a3.x = fmaf(v3.x, w3, a3.x); a3.y = fmaf(v3.y, w3, a3.y);
        a3.z = fmaf(v3.z, w3, a3.z); a3.w = fmaf(v3.w, w3, a3.w);
    }
    for (; e < end; e++) {
        int c = g_colidx[e];
        float w = g_w[e];
        float4 vv = T(h[(size_t)c * s4 + c4off + f4]);
        a0.x = fmaf(vv.x, w, a0.x); a0.y = fmaf(vv.y, w, a0.y);
        a0.z = fmaf(vv.z, w, a0.z); a0.w = fmaf(vv.w, w, a0.w);
    }

    float4 r;
    r.x = (a0.x + a1.x) + (a2.x + a3.x);
    r.y = (a0.y + a1.y) + (a2.y + a3.y);
    r.z = (a0.z + a1.z) + (a2.z + a3.z);
    r.w = (a0.w + a1.w) + (a2.w + a3.w);
    out[(size_t)node * s4 + c4off + f4] = r;
}

// Scalar aggregation for F=40 (layer 3)
template <int F, int NPB>
__global__ void agg_scalar_kernel(const float* __restrict__ h, float* __restrict__ out) {
    int local = threadIdx.x / F;
    int f = threadIdx.x % F;
    int node = blockIdx.x * NPB + local;
    if (node >= NNODES) return;

    int start = g_rowptr[node];
    int end = g_rowptr[node + 1];
    float di = g_dinv[node];
    float acc0 = di * di * h[(size_t)node * F + f];
    float acc1 = 0.f, acc2 = 0.f, acc3 = 0.f;

    int e = start;
    for (; e + 4 <= end; e += 4) {
        int c0 = g_colidx[e + 0], c1 = g_colidx[e + 1];
        int c2 = g_colidx[e + 2], c3 = g_colidx[e + 3];
        float w0 = g_w[e + 0], w1 = g_w[e + 1];
        float w2 = g_w[e + 2], w3 = g_w[e + 3];
        acc0 = fmaf(w0, h[(size_t)c0 * F + f], acc0);
        acc1 = fmaf(w1, h[(size_t)c1 * F + f], acc1);
        acc2 = fmaf(w2, h[(size_t)c2 * F + f], acc2);
        acc3 = fmaf(w3, h[(size_t)c3 * F + f], acc3);
    }
    for (; e < end; e++)
        acc0 = fmaf(g_w[e], h[(size_t)g_colidx[e] * F + f], acc0);

    out[(size_t)node * F + f] = (acc0 + acc1) + (acc2 + acc3);
}

// ---------------------------------------------------------------------------
// TF32 tensor-core GEMM: C[M,Nreal] = A[M,K] @ B[K,Nreal]
// BM x BN block tile, BK=32, 256 threads = 8 warps (4m x 2n).
// FUSE: apply y = relu(a*scale[k]+shift[k]) to A elements while loading.
// ---------------------------------------------------------------------------
template <int BM, int BN, bool FUSE>
__global__ __launch_bounds__(256) void gemm_tf32_kernel(
    int M, int K, int Nreal,
    const float* __restrict__ A, const float* __restrict__ B, float* __restrict__ C,
    const float* __restrict__ scale, const float* __restrict__ shift)
{
    constexpr int BK = 32;
    constexpr int LDA = BK + 4;   // 36: conflict-free frag loads, 16B-aligned stores
    constexpr int LDB = BN + 8;   // conflict-free B frag loads
    __shared__ uint32_t As[BM * LDA];
    __shared__ uint32_t Bs[BK * LDB];

    const int tid = threadIdx.x;
    const int lane = tid & 31;
    const int warp = tid >> 5;
    const int brow = blockIdx.x * BM;
    const int bcol = blockIdx.y * BN;

    constexpr int WTM = BM / 4;
    constexpr int WTN = BN / 2;
    constexpr int MT = WTM / 16;
    constexpr int NT = WTN / 8;
    const int warpRow = (warp & 3) * WTM;
    const int warpCol = (warp >> 2) * WTN;

    float c[MT][NT][4] = {};

    const int aRow = tid >> 3;          // 0..31
    const int aCol = (tid & 7) * 4;     // 0..28

    constexpr int BNV = BN / 4;
    const int bRow = tid / BNV;
    const int bColv = (tid % BNV) * 4;
    constexpr int BSTEP = 256 / BNV;

    for (int k0 = 0; k0 < K; k0 += BK) {
        float4 sc, sh;
        if (FUSE) {
            sc = *(const float4*)(scale + k0 + aCol);
            sh = *(const float4*)(shift + k0 + aCol);
        }
        #pragma unroll
        for (int r = 0; r < BM; r += 32) {
            int gr = brow + aRow + r;
            float4 v = make_float4(0.f, 0.f, 0.f, 0.f);
            if (gr < M) v = *(const float4*)(A + (size_t)gr * K + k0 + aCol);
            if (FUSE) {
                v.x = fmaxf(fmaf(v.x, sc.x, sh.x), 0.f);
                v.y = fmaxf(fmaf(v.y, sc.y, sh.y), 0.f);
                v.z = fmaxf(fmaf(v.z, sc.z, sh.z), 0.f);
                v.w = fmaxf(fmaf(v.w, sc.w, sh.w), 0.f);
            }
            uint4 u = make_uint4(f2tf(v.x), f2tf(v.y), f2tf(v.z), f2tf(v.w));
            *(uint4*)&As[(aRow + r) * LDA + aCol] = u;
        }
        #pragma unroll
        for (int r = bRow; r < BK; r += BSTEP) {
            int gc = bcol + bColv;
            float4 v = make_float4(0.f, 0.f, 0.f, 0.f);
            if (gc < Nreal) v = *(const float4*)(B + (size_t)(k0 + r) * Nreal + gc);
            uint4 u = make_uint4(f2tf(v.x), f2tf(v.y), f2tf(v.z), f2tf(v.w));
            *(uint4*)&Bs[r * LDB + bColv] = u;
        }
        __syncthreads();

        #pragma unroll
        for (int kk = 0; kk < BK / 8; kk++) {
            uint32_t a[MT][4], b[NT][2];
            #pragma unroll
            for (int i = 0; i < MT; i++) {
                int r0 = warpRow + i * 16 + (lane >> 2);
                int cc = kk * 8 + (lane & 3);
                a[i][0] = As[r0 * LDA + cc];
                a[i][1] = As[(r0 + 8) * LDA + cc];
                a[i][2] = As[r0 * LDA + cc + 4];
                a[i][3] = As[(r0 + 8) * LDA + cc + 4];
            }
            #pragma unroll
            for (int j = 0; j < NT; j++) {
                int cc = warpCol + j * 8 + (lane >> 2);
                int r0 = kk * 8 + (lane & 3);
                b[j][0] = Bs[r0 * LDB + cc];
                b[j][1] = Bs[(r0 + 4) * LDB + cc];
            }
            #pragma unroll
            for (int i = 0; i < MT; i++)
                #pragma unroll
                for (int j = 0; j < NT; j++)
                    mma_tf32(c[i][j], a[i], b[j]);
        }
        __syncthreads();
    }

    #pragma unroll
    for (int i = 0; i < MT; i++) {
        int r0 = brow + warpRow + i * 16 + (lane >> 2);
        #pragma unroll
        for (int j = 0; j < NT; j++) {
            int col = bcol + warpCol + j * 8 + (lane & 3) * 2;
            if (col < Nreal) {
                if (r0 < M) {
                    float2 v = make_float2(c[i][j][0], c[i][j][1]);
                    *(float2*)(C + (size_t)r0 * Nreal + col) = v;
                }
                if (r0 + 8 < M) {
                    float2 v = make_float2(c[i][j][2], c[i][j][3]);
                    *(float2*)(C + (size_t)(r0 + 8) * Nreal + col) = v;
                }
            }
        }
    }
}

// ---------------------------------------------------------------------------
// BatchNorm stats
// ---------------------------------------------------------------------------
__global__ void bn_zero_kernel() {
    int f = threadIdx.x;
    g_sum[f] = 0.0;
    g_sumsq[f] = 0.0;
}

__global__ void bn_stats_kernel(const float* __restrict__ h) {
    const int ROWS = 128;
    int f = threadIdx.x;
    int r0 = blockIdx.x * ROWS;
    int r1 = r0 + ROWS; if (r1 > NNODES) r1 = NNODES;
    float s = 0.f, s2 = 0.f;
    for (int r = r0; r < r1; r++) {
        float v = h[(size_t)r * 256 + f];
        s += v;
        s2 = fmaf(v, v, s2);
    }
    atomicAdd(&g_sum[f], (double)s);
    atomicAdd(&g_sumsq[f], (double)s2);
}

__global__ void bn_finalize_kernel(const float* __restrict__ gamma,
                                   const float* __restrict__ beta) {
    int f = threadIdx.x;
    double mu = g_sum[f] / (double)NNODES;
    double var = g_sumsq[f] / (double)NNODES - mu * mu;
    float sc = gamma[f] * rsqrtf((float)var + BN_EPS);
    g_scale[f] = sc;
    g_shift[f] = beta[f] - (float)mu * sc;
}

// ---------------------------------------------------------------------------
// log_softmax over 40 classes (one warp per node), fused +b3
// ---------------------------------------------------------------------------
__global__ void logsoftmax_kernel(const float* __restrict__ in,
                                  const float* __restrict__ b3,
                                  float* __restrict__ out) {
    int warp = (blockIdx.x * blockDim.x + threadIdx.x) >> 5;
    int lane = threadIdx.x & 31;
    if (warp >= NNODES) return;
    const float* r = in + (size_t)warp * 40;
    float v0 = r[lane] + b3[lane];
    bool has2 = (lane + 32) < 40;
    float v1 = has2 ? (r[lane + 32] + b3[lane + 32]) : -INFINITY;

    float m = fmaxf(v0, v1);
    #pragma unroll
    for (int o = 16; o > 0; o >>= 1) m = fmaxf(m, __shfl_xor_sync(0xFFFFFFFFu, m, o));

    float s = expf(v0 - m) + (has2 ? expf(v1 - m) : 0.f);
    #pragma unroll
    for (int o = 16; o > 0; o >>= 1) s += __shfl_xor_sync(0xFFFFFFFFu, s, o);

    float lse = m + logf(s);
    out[(size_t)warp * 40 + lane] = v0 - lse;
    if (has2) out[(size_t)warp * 40 + lane + 32] = v1 - lse;
}

// ---------------------------------------------------------------------------
// Launch
// ---------------------------------------------------------------------------
extern "C" void kernel_launch(void* const* d_in, const int* in_sizes, int n_in,
                              void* d_out, int out_size) {
    const float* x      = (const float*)d_in[0];
    const int*   ei     = (const int*)d_in[1];
    const float* W1     = (const float*)d_in[2];
    const float* gamma1 = (const float*)d_in[4];
    const float* beta1  = (const float*)d_in[5];
    const float* W2     = (const float*)d_in[6];
    const float* gamma2 = (const float*)d_in[8];
    const float* beta2  = (const float*)d_in[9];
    const float* W3     = (const float*)d_in[10];
    const float* b3     = (const float*)d_in[11];
    float* out = (float*)d_out;

    const int* row = ei;
    const int* col = ei + NEDGES;

    float *buf0, *buf1, *buf2, *scale_p, *shift_p;
    cudaGetSymbolAddress((void**)&buf0, g_buf0);
    cudaGetSymbolAddress((void**)&buf1, g_buf1);
    cudaGetSymbolAddress((void**)&buf2, g_buf2);
    cudaGetSymbolAddress((void**)&scale_p, g_scale);
    cudaGetSymbolAddress((void**)&shift_p, g_shift);

    const int EB = (NEDGES + 255) / 256;
    const int NB = (NNODES + 255) / 256;
    const int GROWS = (NNODES + 127) / 128;   // 1563

    // ---- CSR build ----
    zero_counts_kernel<<<NB, 256>>>();
    count_kernel<<<EB, 256>>>(row);
    dinv_kernel<<<NB, 256>>>();
    scan_block_sums_kernel<<<SCAN_BLOCKS, 1024>>>();
    scan_bsums_kernel<<<1, 256>>>();
    scan_write_kernel<<<SCAN_BLOCKS, 1024>>>();
    fill_kernel<<<EB, 256>>>(row, col);

    // ---- Layer 1: agg(x) -> tf32 GEMM 128->256 -> BN stats ----
    agg_vec_kernel<32, 8, false><<<(NNODES + 7) / 8, 256>>>(
        (const float4*)x, (float4*)buf0, 32, 0);
    gemm_tf32_kernel<128, 128, false><<<dim3(GROWS, 2), 256>>>(
        NNODES, 128, 256, buf0, W1, buf1, nullptr, nullptr);
    bn_zero_kernel<<<1, 256>>>();
    bn_stats_kernel<<<GROWS, 256>>>(buf1);
    bn_finalize_kernel<<<1, 256>>>(gamma1, beta1);

    // ---- Layer 2: agg(BNReLU(h1)) in 2 feature halves -> GEMM 256->256 ----
    agg_vec_kernel<32, 8, true><<<(NNODES + 7) / 8, 256>>>(
        (const float4*)buf1, (float4*)buf0, 64, 0);
    agg_vec_kernel<32, 8, true><<<(NNODES + 7) / 8, 256>>>(
        (const float4*)buf1, (float4*)buf0, 64, 32);
    gemm_tf32_kernel<128, 128, false><<<dim3(GROWS, 2), 256>>>(
        NNODES, 256, 256, buf0, W2, buf1, nullptr, nullptr);
    bn_zero_kernel<<<1, 256>>>();
    bn_stats_kernel<<<GROWS, 256>>>(buf1);
    bn_finalize_kernel<<<1, 256>>>(gamma2, beta2);

    // ---- Layer 3: GEMM (BNReLU fused into A-load) 256->40 -> agg -> lsm ----
    gemm_tf32_kernel<128, 64, true><<<dim3(GROWS, 1), 256>>>(
        NNODES, 256, 40, buf1, W3, buf0, scale_p, shift_p);
    agg_scalar_kernel<40, 6><<<(NNODES + 5) / 6, 240>>>(buf0, buf2);
    logsoftmax_kernel<<<(NNODES + 7) / 8, 256>>>(buf2, b3, out);
}

// round 3
// speedup vs baseline: 2.9732x; 1.6061x over previous
#include <cuda_runtime.h>
#include <cuda_fp16.h>
#include <math.h>
#include <stdint.h>

#define NNODES 200000
#define NEDGES 3200000
#define BN_EPS 1e-5f
#define SCAN_BLOCKS ((NNODES + 1023) / 1024)   // 196

// ---------------------------------------------------------------------------
// Static device scratch
// ---------------------------------------------------------------------------
__device__ float  g_buf1[(size_t)NNODES * 256];  // fp32 GEMM outputs (shared L1/L2)
__device__ float  g_buf3[(size_t)NNODES * 40];   // GEMM3 out
__device__ float  g_buf4[(size_t)NNODES * 40];   // agg3 out

__device__ __half g_xh [(size_t)NNODES * 128];   // x in fp16
__device__ __half g_a1h[(size_t)NNODES * 128];   // agg1 out fp16
__device__ __half g_h1h[(size_t)NNODES * 256];   // BNReLU(h1) fp16
__device__ __half g_a2h[(size_t)NNODES * 256];   // agg2 out fp16

__device__ __half g_wt1[256 * 128];              // W1^T fp16 [N][K]
__device__ __half g_wt2[256 * 256];
__device__ __half g_wt3[64 * 256];               // padded N 40->64

__device__ int   g_cnt[NNODES];
__device__ int   g_cur[NNODES];
__device__ int   g_rowptr[NNODES + 1];
__device__ float g_dinv[NNODES];
__device__ int   g_colidx[NEDGES];
__device__ float g_w[NEDGES];

__device__ int   g_bsum[256];
__device__ int   g_boff[256];

__device__ double g_sum[256];
__device__ double g_sumsq[256];
__device__ float  g_scale[256];
__device__ float  g_shift[256];

// ---------------------------------------------------------------------------
// Helpers
// ---------------------------------------------------------------------------
__device__ __forceinline__ void mma_f16(float* c, const uint32_t* a, const uint32_t* b) {
    asm volatile(
        "mma.sync.aligned.m16n8k16.row.col.f32.f16.f16.f32 "
        "{%0,%1,%2,%3}, {%4,%5,%6,%7}, {%8,%9}, {%0,%1,%2,%3};\n"
        : "+f"(c[0]), "+f"(c[1]), "+f"(c[2]), "+f"(c[3])
        : "r"(a[0]), "r"(a[1]), "r"(a[2]), "r"(a[3]), "r"(b[0]), "r"(b[1]));
}

__device__ __forceinline__ void unpack8(uint4 u, float* f) {
    const __half2* p = reinterpret_cast<const __half2*>(&u);
    #pragma unroll
    for (int i = 0; i < 4; i++) {
        float2 t = __half22float2(p[i]);
        f[2 * i] = t.x;
        f[2 * i + 1] = t.y;
    }
}

__device__ __forceinline__ uint4 pack8(const float* f) {
    uint4 u;
    __half2* p = reinterpret_cast<__half2*>(&u);
    #pragma unroll
    for (int i = 0; i < 4; i++)
        p[i] = __floats2half2_rn(f[2 * i], f[2 * i + 1]);
    return u;
}

__device__ __forceinline__ int warp_incl_scan(int v) {
    #pragma unroll
    for (int o = 1; o < 32; o <<= 1) {
        int n = __shfl_up_sync(0xFFFFFFFFu, v, o);
        if ((threadIdx.x & 31) >= o) v += n;
    }
    return v;
}

// ---------------------------------------------------------------------------
// CSR build
// ---------------------------------------------------------------------------
__global__ void zero_counts_kernel() {
    int i = blockIdx.x * blockDim.x + threadIdx.x;
    if (i < NNODES) { g_cnt[i] = 0; g_cur[i] = 0; }
}

__global__ void count_kernel(const int* __restrict__ row) {
    int e = blockIdx.x * blockDim.x + threadIdx.x;
    if (e < NEDGES) atomicAdd(&g_cnt[row[e]], 1);
}

__global__ void dinv_kernel() {
    int i = blockIdx.x * blockDim.x + threadIdx.x;
    if (i < NNODES) g_dinv[i] = rsqrtf((float)(g_cnt[i] + 1));
}

__global__ __launch_bounds__(1024) void scan_block_sums_kernel() {
    __shared__ int sm[32];
    int i = blockIdx.x * 1024 + threadIdx.x;
    int v = (i < NNODES) ? g_cnt[i] : 0;
    #pragma unroll
    for (int o = 16; o > 0; o >>= 1) v += __shfl_down_sync(0xFFFFFFFFu, v, o);
    if ((threadIdx.x & 31) == 0) sm[threadIdx.x >> 5] = v;
    __syncthreads();
    if (threadIdx.x < 32) {
        int s = sm[threadIdx.x];
        #pragma unroll
        for (int o = 16; o > 0; o >>= 1) s += __shfl_down_sync(0xFFFFFFFFu, s, o);
        if (threadIdx.x == 0) g_bsum[blockIdx.x] = s;
    }
}

__global__ void scan_bsums_kernel() {
    __shared__ int wsum[8];
    int t = threadIdx.x;
    int v = (t < SCAN_BLOCKS) ? g_bsum[t] : 0;
    int incl = warp_incl_scan(v);
    if ((t & 31) == 31) wsum[t >> 5] = incl;
    __syncthreads();
    if (t < 8) {
        int s = wsum[t];
        #pragma unroll
        for (int o = 1; o < 8; o <<= 1) {
            int n = __shfl_up_sync(0xFFu, s, o);
            if (t >= o) s += n;
        }
        wsum[t] = s;
    }
    __syncthreads();
    int warp = t >> 5;
    if (warp > 0) incl += wsum[warp - 1];
    g_boff[t] = incl - v;
}

__global__ __launch_bounds__(1024) void scan_write_kernel() {
    __shared__ int wsum[32];
    int i = blockIdx.x * 1024 + threadIdx.x;
    int v = (i < NNODES) ? g_cnt[i] : 0;
    int incl = warp_incl_scan(v);
    int lane = threadIdx.x & 31;
    int warp = threadIdx.x >> 5;
    if (lane == 31) wsum[warp] = incl;
    __syncthreads();
    if (threadIdx.x < 32) wsum[threadIdx.x] = warp_incl_scan(wsum[threadIdx.x]);
    __syncthreads();
    if (warp > 0) incl += wsum[warp - 1];
    if (i < NNODES) g_rowptr[i] = g_boff[blockIdx.x] + incl - v;
    if (i == 0) g_rowptr[NNODES] = NEDGES;
}

__global__ void fill_kernel(const int* __restrict__ row, const int* __restrict__ col) {
    int e = blockIdx.x * blockDim.x + threadIdx.x;
    if (e >= NEDGES) return;
    int d = row[e];
    int s = col[e];
    int p = g_rowptr[d] + atomicAdd(&g_cur[d], 1);
    g_colidx[p] = s;
    g_w[p] = g_dinv[d] * g_dinv[s];
}

// ---------------------------------------------------------------------------
// fp32 -> fp16 conversion, optional fused BN+ReLU (per 256-wide feature row)
// ---------------------------------------------------------------------------
template <bool BN>
__global__ void f32_to_f16_kernel(const float4* __restrict__ in,
                                  uint2* __restrict__ out, size_t n4, int f4) {
    size_t idx = (size_t)blockIdx.x * blockDim.x + threadIdx.x;
    if (idx >= n4) return;
    float4 v = in[idx];
    if (BN) {
        int c = (int)(idx % f4) * 4;
        float4 sc = *((const float4*)g_scale + (c >> 2));
        float4 sh = *((const float4*)g_shift + (c >> 2));
        v.x = fmaxf(fmaf(v.x, sc.x, sh.x), 0.f);
        v.y = fmaxf(fmaf(v.y, sc.y, sh.y), 0.f);
        v.z = fmaxf(fmaf(v.z, sc.z, sh.z), 0.f);
        v.w = fmaxf(fmaf(v.w, sc.w, sh.w), 0.f);
    }
    uint2 r;
    *reinterpret_cast<__half2*>(&r.x) = __floats2half2_rn(v.x, v.y);
    *reinterpret_cast<__half2*>(&r.y) = __floats2half2_rn(v.z, v.w);
    out[idx] = r;
}

// W [K][N] fp32  ->  Wt [Npad][K] fp16 (transposed, zero-padded)
__global__ void convert_w_kernel(const float* __restrict__ W, __half* __restrict__ Wt,
                                 int K, int N, int Npad) {
    int idx = blockIdx.x * blockDim.x + threadIdx.x;
    if (idx >= K * Npad) return;
    int n = idx / K, k = idx % K;
    Wt[idx] = (n < N) ? __float2half(W[(size_t)k * N + n]) : __half(0);
}

// ---------------------------------------------------------------------------
// fp16 pull aggregation: out[i] = w_self*h[i] + sum_e w[e]*h[col[e]]
// Each lane owns 8 features (one uint4).
// ---------------------------------------------------------------------------
template <int F8, int NPB>
__global__ __launch_bounds__(F8 * NPB) void agg_f16_kernel(
    const uint4* __restrict__ h, uint4* __restrict__ out)
{
    int f = threadIdx.x % F8;
    int node = blockIdx.x * NPB + threadIdx.x / F8;
    if (node >= NNODES) return;

    int start = g_rowptr[node];
    int end = g_rowptr[node + 1];
    float di = g_dinv[node];
    float ws = di * di;

    float a[8], acc0[8], acc1[8];
    unpack8(h[(size_t)node * F8 + f], a);
    #pragma unroll
    for (int i = 0; i < 8; i++) { acc0[i] = a[i] * ws; acc1[i] = 0.f; }

    int e = start;
    for (; e + 4 <= end; e += 4) {
        int c0 = g_colidx[e + 0], c1 = g_colidx[e + 1];
        int c2 = g_colidx[e + 2], c3 = g_colidx[e + 3];
        float w0 = g_w[e + 0], w1 = g_w[e + 1], w2 = g_w[e + 2], w3 = g_w[e + 3];
        uint4 u0 = h[(size_t)c0 * F8 + f];
        uint4 u1 = h[(size_t)c1 * F8 + f];
        uint4 u2 = h[(size_t)c2 * F8 + f];
        uint4 u3 = h[(size_t)c3 * F8 + f];
        float v0[8], v1[8], v2[8], v3[8];
        unpack8(u0, v0); unpack8(u1, v1); unpack8(u2, v2); unpack8(u3, v3);
        #pragma unroll
        for (int i = 0; i < 8; i++) {
            acc0[i] = fmaf(v0[i], w0, acc0[i]);
            acc1[i] = fmaf(v1[i], w1, acc1[i]);
            acc0[i] = fmaf(v2[i], w2, acc0[i]);
            acc1[i] = fmaf(v3[i], w3, acc1[i]);
        }
    }
    for (; e < end; e++) {
        int c = g_colidx[e];
        float w = g_w[e];
        float v[8];
        unpack8(h[(size_t)c * F8 + f], v);
        #pragma unroll
        for (int i = 0; i < 8; i++) acc0[i] = fmaf(v[i], w, acc0[i]);
    }

    float r[8];
    #pragma unroll
    for (int i = 0; i < 8; i++) r[i] = acc0[i] + acc1[i];
    out[(size_t)node * F8 + f] = pack8(r);
}

// Scalar fp32 aggregation for F=40 (layer 3 output)
template <int F, int NPB>
__global__ void agg_scalar_kernel(const float* __restrict__ h, float* __restrict__ out) {
    int local = threadIdx.x / F;
    int f = threadIdx.x % F;
    int node = blockIdx.x * NPB + local;
    if (node >= NNODES) return;

    int start = g_rowptr[node];
    int end = g_rowptr[node + 1];
    float di = g_dinv[node];
    float acc0 = di * di * h[(size_t)node * F + f];
    float acc1 = 0.f, acc2 = 0.f, acc3 = 0.f;

    int e = start;
    for (; e + 4 <= end; e += 4) {
        int c0 = g_colidx[e + 0], c1 = g_colidx[e + 1];
        int c2 = g_colidx[e + 2], c3 = g_colidx[e + 3];
        float w0 = g_w[e + 0], w1 = g_w[e + 1];
        float w2 = g_w[e + 2], w3 = g_w[e + 3];
        acc0 = fmaf(w0, h[(size_t)c0 * F + f], acc0);
        acc1 = fmaf(w1, h[(size_t)c1 * F + f], acc1);
        acc2 = fmaf(w2, h[(size_t)c2 * F + f], acc2);
        acc3 = fmaf(w3, h[(size_t)c3 * F + f], acc3);
    }
    for (; e < end; e++)
        acc0 = fmaf(g_w[e], h[(size_t)g_colidx[e] * F + f], acc0);

    out[(size_t)node * F + f] = (acc0 + acc1) + (acc2 + acc3);
}

// ---------------------------------------------------------------------------
// fp16 tensor-core GEMM: C[M,Nreal] = A[M,K] @ Wt^T   (Wt is [Npad][K] fp16)
// AF32BN: A is fp32, apply y=relu(a*scale[k]+shift[k]) while loading.
// 256 threads = 8 warps (4m x 2n); BK=32 (two k16 steps).
// ---------------------------------------------------------------------------
template <int BM, int BN, bool AF32BN>
__global__ __launch_bounds__(256) void gemm_f16_kernel(
    int M, int K, int Nreal,
    const __half* __restrict__ Ah, const float* __restrict__ Af,
    const __half* __restrict__ Wt, float* __restrict__ C)
{
    constexpr int BK = 32;
    constexpr int LDA = BK + 8;   // halves; row stride 80B
    constexpr int LDB = BK + 8;
    __shared__ __half As[BM * LDA];
    __shared__ __half Bs[BN * LDB];   // transposed: Bs[n][k]

    const int tid = threadIdx.x;
    const int lane = tid & 31;
    const int warp = tid >> 5;
    const int brow = blockIdx.x * BM;
    const int bcol = blockIdx.y * BN;

    constexpr int WTM = BM / 4;          // 32
    constexpr int WTN = BN / 2;          // 64 or 32
    constexpr int MT = WTM / 16;         // 2
    constexpr int NT = WTN / 8;          // 8 or 4
    const int warpRow = (warp & 3) * WTM;
    const int warpCol = (warp >> 2) * WTN;
    const int g = lane >> 2;             // group id 0..7
    const int t2 = (lane & 3) * 2;       // 0,2,4,6

    float c[MT][NT][4] = {};

    for (int k0 = 0; k0 < K; k0 += BK) {
        // ---- A tile ----
        if (!AF32BN) {
            const int aRow = tid >> 2;           // 0..63
            const int aChunk = (tid & 3) * 8;    // halves
            #pragma unroll
            for (int r = 0; r < BM; r += 64) {
                int gr = brow + aRow + r;
                uint4 v = make_uint4(0, 0, 0, 0);
                if (gr < M) v = *(const uint4*)(Ah + (size_t)gr * K + k0 + aChunk);
                *(uint4*)&As[(aRow + r) * LDA + aChunk] = v;
            }
        } else {
            const int aRow = tid >> 3;           // 0..31
            const int aCol = (tid & 7) * 4;
            float4 sc = *(const float4*)(g_scale + k0 + aCol);
            float4 sh = *(const float4*)(g_shift + k0 + aCol);
            #pragma unroll
            for (int r = 0; r < BM; r += 32) {
                int gr = brow + aRow + r;
                float4 v = make_float4(0.f, 0.f, 0.f, 0.f);
                if (gr < M) v = *(const float4*)(Af + (size_t)gr * K + k0 + aCol);
                v.x = fmaxf(fmaf(v.x, sc.x, sh.x), 0.f);
                v.y = fmaxf(fmaf(v.y, sc.y, sh.y), 0.f);
                v.z = fmaxf(fmaf(v.z, sc.z, sh.z), 0.f);
                v.w = fmaxf(fmaf(v.w, sc.w, sh.w), 0.f);
                uint2 u;
                *reinterpret_cast<__half2*>(&u.x) = __floats2half2_rn(v.x, v.y);
                *reinterpret_cast<__half2*>(&u.y) = __floats2half2_rn(v.z, v.w);
                *(uint2*)&As[(aRow + r) * LDA + aCol] = u;
            }
        }
        // ---- B tile (already [n][k] in global) ----
        {
            const int bRow = tid >> 2;           // n: 0..63
            const int bChunk = (tid & 3) * 8;
            #pragma unroll
            for (int n = 0; n < BN; n += 64) {
                *(uint4*)&Bs[(bRow + n) * LDB + bChunk] =
                    *(const uint4*)(Wt + (size_t)(bcol + bRow + n) * K + k0 + bChunk);
            }
        }
        __syncthreads();

        #pragma unroll
        for (int kk = 0; kk < BK / 16; kk++) {
            uint32_t a[MT][4], b[NT][2];
            #pragma unroll
            for (int i = 0; i < MT; i++) {
                int r0 = warpRow + i * 16 + g;
                int cc = kk * 16 + t2;
                a[i][0] = *(const uint32_t*)&As[r0 * LDA + cc];
                a[i][1] = *(const uint32_t*)&As[(r0 + 8) * LDA + cc];
                a[i][2] = *(const uint32_t*)&As[r0 * LDA + cc + 8];
                a[i][3] = *(const uint32_t*)&As[(r0 + 8) * LDA + cc + 8];
            }
            #pragma unroll
            for (int j = 0; j < NT; j++) {
                int n = warpCol + j * 8 + g;
                int cc = kk * 16 + t2;
                b[j][0] = *(const uint32_t*)&Bs[n * LDB + cc];
                b[j][1] = *(const uint32_t*)&Bs[n * LDB + cc + 8];
            }
            #pragma unroll
            for (int i = 0; i < MT; i++)
                #pragma unroll
                for (int j = 0; j < NT; j++)
                    mma_f16(c[i][j], a[i], b[j]);
        }
        __syncthreads();
    }

    #pragma unroll
    for (int i = 0; i < MT; i++) {
        int r0 = brow + warpRow + i * 16 + g;
        #pragma unroll
        for (int j = 0; j < NT; j++) {
            int col = bcol + warpCol + j * 8 + t2;
            if (col < Nreal) {
                if (r0 < M)
                    *(float2*)(C + (size_t)r0 * Nreal + col) = make_float2(c[i][j][0], c[i][j][1]);
                if (r0 + 8 < M)
                    *(float2*)(C + (size_t)(r0 + 8) * Nreal + col) = make_float2(c[i][j][2], c[i][j][3]);
            }
        }
    }
}

// ---------------------------------------------------------------------------
// BatchNorm stats
// ---------------------------------------------------------------------------
__global__ void bn_zero_kernel() {
    int f = threadIdx.x;
    g_sum[f] = 0.0;
    g_sumsq[f] = 0.0;
}

__global__ void bn_stats_kernel(const float* __restrict__ h) {
    const int ROWS = 128;
    int f = threadIdx.x;
    int r0 = blockIdx.x * ROWS;
    int r1 = r0 + ROWS; if (r1 > NNODES) r1 = NNODES;
    float s = 0.f, s2 = 0.f;
    for (int r = r0; r < r1; r++) {
        float v = h[(size_t)r * 256 + f];
        s += v;
        s2 = fmaf(v, v, s2);
    }
    atomicAdd(&g_sum[f], (double)s);
    atomicAdd(&g_sumsq[f], (double)s2);
}

__global__ void bn_finalize_kernel(const float* __restrict__ gamma,
                                   const float* __restrict__ beta) {
    int f = threadIdx.x;
    double mu = g_sum[f] / (double)NNODES;
    double var = g_sumsq[f] / (double)NNODES - mu * mu;
    float sc = gamma[f] * rsqrtf((float)var + BN_EPS);
    g_scale[f] = sc;
    g_shift[f] = beta[f] - (float)mu * sc;
}

// ---------------------------------------------------------------------------
// log_softmax over 40 classes (one warp per node), fused +b3
// ---------------------------------------------------------------------------
__global__ void logsoftmax_kernel(const float* __restrict__ in,
                                  const float* __restrict__ b3,
                                  float* __restrict__ out) {
    int warp = (blockIdx.x * blockDim.x + threadIdx.x) >> 5;
    int lane = threadIdx.x & 31;
    if (warp >= NNODES) return;
    const float* r = in + (size_t)warp * 40;
    float v0 = r[lane] + b3[lane];
    bool has2 = (lane + 32) < 40;
    float v1 = has2 ? (r[lane + 32] + b3[lane + 32]) : -INFINITY;

    float m = fmaxf(v0, v1);
    #pragma unroll
    for (int o = 16; o > 0; o >>= 1) m = fmaxf(m, __shfl_xor_sync(0xFFFFFFFFu, m, o));

    float s = expf(v0 - m) + (has2 ? expf(v1 - m) : 0.f);
    #pragma unroll
    for (int o = 16; o > 0; o >>= 1) s += __shfl_xor_sync(0xFFFFFFFFu, s, o);

    float lse = m + logf(s);
    out[(size_t)warp * 40 + lane] = v0 - lse;
    if (has2) out[(size_t)warp * 40 + lane + 32] = v1 - lse;
}

// ---------------------------------------------------------------------------
// Launch
// ---------------------------------------------------------------------------
extern "C" void kernel_launch(void* const* d_in, const int* in_sizes, int n_in,
                              void* d_out, int out_size) {
    const float* x      = (const float*)d_in[0];
    const int*   ei     = (const int*)d_in[1];
    const float* W1     = (const float*)d_in[2];
    const float* gamma1 = (const float*)d_in[4];
    const float* beta1  = (const float*)d_in[5];
    const float* W2     = (const float*)d_in[6];
    const float* gamma2 = (const float*)d_in[8];
    const float* beta2  = (const float*)d_in[9];
    const float* W3     = (const float*)d_in[10];
    const float* b3     = (const float*)d_in[11];
    float* out = (float*)d_out;

    const int* row = ei;
    const int* col = ei + NEDGES;

    float *buf1, *buf3, *buf4;
    __half *xh, *a1h, *h1h, *a2h, *wt1, *wt2, *wt3;
    cudaGetSymbolAddress((void**)&buf1, g_buf1);
    cudaGetSymbolAddress((void**)&buf3, g_buf3);
    cudaGetSymbolAddress((void**)&buf4, g_buf4);
    cudaGetSymbolAddress((void**)&xh,  g_xh);
    cudaGetSymbolAddress((void**)&a1h, g_a1h);
    cudaGetSymbolAddress((void**)&h1h, g_h1h);
    cudaGetSymbolAddress((void**)&a2h, g_a2h);
    cudaGetSymbolAddress((void**)&wt1, g_wt1);
    cudaGetSymbolAddress((void**)&wt2, g_wt2);
    cudaGetSymbolAddress((void**)&wt3, g_wt3);

    const int EB = (NEDGES + 255) / 256;
    const int NB = (NNODES + 255) / 256;
    const int GROWS = (NNODES + 127) / 128;   // 1563

    // ---- Prep: weight transpose+fp16, x -> fp16 ----
    convert_w_kernel<<<(256 * 128 + 255) / 256, 256>>>(W1, wt1, 128, 256, 256);
    convert_w_kernel<<<(256 * 256 + 255) / 256, 256>>>(W2, wt2, 256, 256, 256);
    convert_w_kernel<<<(64 * 256 + 255) / 256, 256>>>(W3, wt3, 256, 40, 64);
    {
        size_t n4 = (size_t)NNODES * 128 / 4;
        f32_to_f16_kernel<false><<<(int)((n4 + 255) / 256), 256>>>(
            (const float4*)x, (uint2*)xh, n4, 32);
    }

    // ---- CSR build ----
    zero_counts_kernel<<<NB, 256>>>();
    count_kernel<<<EB, 256>>>(row);
    dinv_kernel<<<NB, 256>>>();
    scan_block_sums_kernel<<<SCAN_BLOCKS, 1024>>>();
    scan_bsums_kernel<<<1, 256>>>();
    scan_write_kernel<<<SCAN_BLOCKS, 1024>>>();
    fill_kernel<<<EB, 256>>>(row, col);

    // ---- Layer 1: agg(xh) -> fp16 GEMM 128->256 -> BN stats -> h1h fp16 ----
    agg_f16_kernel<16, 16><<<NNODES / 16, 256>>>((const uint4*)xh, (uint4*)a1h);
    gemm_f16_kernel<128, 128, false><<<dim3(GROWS, 2), 256>>>(
        NNODES, 128, 256, a1h, nullptr, wt1, buf1);
    bn_zero_kernel<<<1, 256>>>();
    bn_stats_kernel<<<GROWS, 256>>>(buf1);
    bn_finalize_kernel<<<1, 256>>>(gamma1, beta1);
    {
        size_t n4 = (size_t)NNODES * 256 / 4;
        f32_to_f16_kernel<true><<<(int)((n4 + 255) / 256), 256>>>(
            (const float4*)buf1, (uint2*)h1h, n4, 64);
    }

    // ---- Layer 2: agg(h1h) single pass -> GEMM 256->256 -> BN stats ----
    agg_f16_kernel<32, 8><<<NNODES / 8, 256>>>((const uint4*)h1h, (uint4*)a2h);
    gemm_f16_kernel<128, 128, false><<<dim3(GROWS, 2), 256>>>(
        NNODES, 256, 256, a2h, nullptr, wt2, buf1);
    bn_zero_kernel<<<1, 256>>>();
    bn_stats_kernel<<<GROWS, 256>>>(buf1);
    bn_finalize_kernel<<<1, 256>>>(gamma2, beta2);

    // ---- Layer 3: GEMM (BNReLU fused into A-load) 256->40 -> agg -> lsm ----
    gemm_f16_kernel<128, 64, true><<<dim3(GROWS, 1), 256>>>(
        NNODES, 256, 40, nullptr, buf1, wt3, buf3);
    agg_scalar_kernel<40, 6><<<(NNODES + 5) / 6, 240>>>(buf3, buf4);
    logsoftmax_kernel<<<(NNODES + 7) / 8, 256>>>(buf4, b3, out);
}

// round 4
// speedup vs baseline: 3.3714x; 1.1339x over previous
#include <cuda_runtime.h>
#include <cuda_fp16.h>
#include <math.h>
#include <stdint.h>

#define NNODES 200000
#define NEDGES 3200000
#define BN_EPS 1e-5f
#define SCAN_BLOCKS ((NNODES + 1023) / 1024)   // 196

// ---------------------------------------------------------------------------
// Static device scratch
// ---------------------------------------------------------------------------
__device__ float  g_buf3[(size_t)NNODES * 40];   // GEMM3 out (fp32)
__device__ float  g_buf4[(size_t)NNODES * 40];   // agg3 out

__device__ __half g_xh [(size_t)NNODES * 128 + 16384];  // x fp16 (+pad)
__device__ __half g_a1h[(size_t)NNODES * 128 + 16384];  // agg1 out
__device__ __half g_h1h[(size_t)NNODES * 256 + 32768];  // h1 raw fp16 (pre-BN)
__device__ __half g_a2h[(size_t)NNODES * 256 + 32768];  // agg2 out
__device__ __half g_h2h[(size_t)NNODES * 256 + 32768];  // h2 raw fp16 (pre-BN)

__device__ __half g_wt1[256 * 128];              // W^T fp16 [N][K]
__device__ __half g_wt2[256 * 256];
__device__ __half g_wt3[64 * 256];               // padded N 40->64

__device__ int   g_cnt[NNODES];
__device__ int   g_cur[NNODES];
__device__ int   g_rowptr[NNODES + 1];
__device__ float g_dinv[NNODES];
__device__ int   g_colidx[NEDGES];
__device__ float g_w[NEDGES];

__device__ int   g_bsum[256];
__device__ int   g_boff[256];

__device__ double g_sum[256];
__device__ double g_sumsq[256];
__device__ float  g_scale[256];
__device__ float  g_shift[256];

// ---------------------------------------------------------------------------
// Helpers
// ---------------------------------------------------------------------------
__device__ __forceinline__ void mma_f16(float* c, const uint32_t* a, const uint32_t* b) {
    asm volatile(
        "mma.sync.aligned.m16n8k16.row.col.f32.f16.f16.f32 "
        "{%0,%1,%2,%3}, {%4,%5,%6,%7}, {%8,%9}, {%0,%1,%2,%3};\n"
        : "+f"(c[0]), "+f"(c[1]), "+f"(c[2]), "+f"(c[3])
        : "r"(a[0]), "r"(a[1]), "r"(a[2]), "r"(a[3]), "r"(b[0]), "r"(b[1]));
}

__device__ __forceinline__ void unpack8(uint4 u, float* f) {
    const __half2* p = reinterpret_cast<const __half2*>(&u);
    #pragma unroll
    for (int i = 0; i < 4; i++) {
        float2 t = __half22float2(p[i]);
        f[2 * i] = t.x;
        f[2 * i + 1] = t.y;
    }
}

__device__ __forceinline__ uint4 pack8(const float* f) {
    uint4 u;
    __half2* p = reinterpret_cast<__half2*>(&u);
    #pragma unroll
    for (int i = 0; i < 4; i++)
        p[i] = __floats2half2_rn(f[2 * i], f[2 * i + 1]);
    return u;
}

__device__ __forceinline__ uint32_t smem_u32(const void* p) {
    return (uint32_t)__cvta_generic_to_shared(p);
}

#define CP_ASYNC16(dst_u32, src_ptr, sz) \
    asm volatile("cp.async.cg.shared.global [%0], [%1], 16, %2;" \
                 :: "r"(dst_u32), "l"(src_ptr), "r"(sz))
#define CP_COMMIT() asm volatile("cp.async.commit_group;")
#define CP_WAIT(N)  asm volatile("cp.async.wait_group %0;" :: "n"(N))

__device__ __forceinline__ int warp_incl_scan(int v) {
    #pragma unroll
    for (int o = 1; o < 32; o <<= 1) {
        int n = __shfl_up_sync(0xFFFFFFFFu, v, o);
        if ((threadIdx.x & 31) >= o) v += n;
    }
    return v;
}

// ---------------------------------------------------------------------------
// CSR build
// ---------------------------------------------------------------------------
__global__ void zero_counts_kernel() {
    int i = blockIdx.x * blockDim.x + threadIdx.x;
    if (i < NNODES) { g_cnt[i] = 0; g_cur[i] = 0; }
}

__global__ void count_kernel(const int* __restrict__ row) {
    int e = blockIdx.x * blockDim.x + threadIdx.x;
    if (e < NEDGES) atomicAdd(&g_cnt[row[e]], 1);
}

__global__ void dinv_kernel() {
    int i = blockIdx.x * blockDim.x + threadIdx.x;
    if (i < NNODES) g_dinv[i] = rsqrtf((float)(g_cnt[i] + 1));
}

__global__ __launch_bounds__(1024) void scan_block_sums_kernel() {
    __shared__ int sm[32];
    int i = blockIdx.x * 1024 + threadIdx.x;
    int v = (i < NNODES) ? g_cnt[i] : 0;
    #pragma unroll
    for (int o = 16; o > 0; o >>= 1) v += __shfl_down_sync(0xFFFFFFFFu, v, o);
    if ((threadIdx.x & 31) == 0) sm[threadIdx.x >> 5] = v;
    __syncthreads();
    if (threadIdx.x < 32) {
        int s = sm[threadIdx.x];
        #pragma unroll
        for (int o = 16; o > 0; o >>= 1) s += __shfl_down_sync(0xFFFFFFFFu, s, o);
        if (threadIdx.x == 0) g_bsum[blockIdx.x] = s;
    }
}

__global__ void scan_bsums_kernel() {
    __shared__ int wsum[8];
    int t = threadIdx.x;
    int v = (t < SCAN_BLOCKS) ? g_bsum[t] : 0;
    int incl = warp_incl_scan(v);
    if ((t & 31) == 31) wsum[t >> 5] = incl;
    __syncthreads();
    if (t < 8) {
        int s = wsum[t];
        #pragma unroll
        for (int o = 1; o < 8; o <<= 1) {
            int n = __shfl_up_sync(0xFFu, s, o);
            if (t >= o) s += n;
        }
        wsum[t] = s;
    }
    __syncthreads();
    int warp = t >> 5;
    if (warp > 0) incl += wsum[warp - 1];
    g_boff[t] = incl - v;
}

__global__ __launch_bounds__(1024) void scan_write_kernel() {
    __shared__ int wsum[32];
    int i = blockIdx.x * 1024 + threadIdx.x;
    int v = (i < NNODES) ? g_cnt[i] : 0;
    int incl = warp_incl_scan(v);
    int lane = threadIdx.x & 31;
    int warp = threadIdx.x >> 5;
    if (lane == 31) wsum[warp] = incl;
    __syncthreads();
    if (threadIdx.x < 32) wsum[threadIdx.x] = warp_incl_scan(wsum[threadIdx.x]);
    __syncthreads();
    if (warp > 0) incl += wsum[warp - 1];
    if (i < NNODES) g_rowptr[i] = g_boff[blockIdx.x] + incl - v;
    if (i == 0) g_rowptr[NNODES] = NEDGES;
}

__global__ void fill_kernel(const int* __restrict__ row, const int* __restrict__ col) {
    int e = blockIdx.x * blockDim.x + threadIdx.x;
    if (e >= NEDGES) return;
    int d = row[e];
    int s = col[e];
    int p = g_rowptr[d] + atomicAdd(&g_cur[d], 1);
    g_colidx[p] = s;
    g_w[p] = g_dinv[d] * g_dinv[s];
}

// ---------------------------------------------------------------------------
// x fp32 -> fp16
// ---------------------------------------------------------------------------
__global__ void f32_to_f16_kernel(const float4* __restrict__ in,
                                  uint2* __restrict__ out, size_t n4) {
    size_t idx = (size_t)blockIdx.x * blockDim.x + threadIdx.x;
    if (idx >= n4) return;
    float4 v = in[idx];
    uint2 r;
    *reinterpret_cast<__half2*>(&r.x) = __floats2half2_rn(v.x, v.y);
    *reinterpret_cast<__half2*>(&r.y) = __floats2half2_rn(v.z, v.w);
    out[idx] = r;
}

// W [K][N] fp32  ->  Wt [Npad][K] fp16 (transposed, zero-padded)
__global__ void convert_w_kernel(const float* __restrict__ W, __half* __restrict__ Wt,
                                 int K, int N, int Npad) {
    int idx = blockIdx.x * blockDim.x + threadIdx.x;
    if (idx >= K * Npad) return;
    int n = idx / K, k = idx % K;
    Wt[idx] = (n < N) ? __float2half(W[(size_t)k * N + n]) : __half(0);
}

// ---------------------------------------------------------------------------
// fp16 pull aggregation. BN: apply relu(v*scale+shift) to every gathered value.
// Each lane owns 8 features (one uint4).
// ---------------------------------------------------------------------------
template <int F8, int NPB, bool BN>
__global__ __launch_bounds__(F8 * NPB) void agg_f16_kernel(
    const uint4* __restrict__ h, uint4* __restrict__ out)
{
    int f = threadIdx.x % F8;
    int node = blockIdx.x * NPB + threadIdx.x / F8;
    if (node >= NNODES) return;

    float sc[8], sh[8];
    if (BN) {
        #pragma unroll
        for (int q = 0; q < 2; q++) {
            float4 a = *((const float4*)g_scale + f * 2 + q);
            float4 b = *((const float4*)g_shift + f * 2 + q);
            sc[q * 4 + 0] = a.x; sc[q * 4 + 1] = a.y; sc[q * 4 + 2] = a.z; sc[q * 4 + 3] = a.w;
            sh[q * 4 + 0] = b.x; sh[q * 4 + 1] = b.y; sh[q * 4 + 2] = b.z; sh[q * 4 + 3] = b.w;
        }
    }

    auto T = [&](float* v) {
        if (BN) {
            #pragma unroll
            for (int i = 0; i < 8; i++)
                v[i] = fmaxf(fmaf(v[i], sc[i], sh[i]), 0.f);
        }
    };

    int start = g_rowptr[node];
    int end = g_rowptr[node + 1];
    float di = g_dinv[node];
    float ws = di * di;

    float a[8], acc0[8], acc1[8];
    unpack8(h[(size_t)node * F8 + f], a);
    T(a);
    #pragma unroll
    for (int i = 0; i < 8; i++) { acc0[i] = a[i] * ws; acc1[i] = 0.f; }

    int e = start;
    for (; e + 4 <= end; e += 4) {
        int c0 = g_colidx[e + 0], c1 = g_colidx[e + 1];
        int c2 = g_colidx[e + 2], c3 = g_colidx[e + 3];
        float w0 = g_w[e + 0], w1 = g_w[e + 1], w2 = g_w[e + 2], w3 = g_w[e + 3];
        uint4 u0 = h[(size_t)c0 * F8 + f];
        uint4 u1 = h[(size_t)c1 * F8 + f];
        uint4 u2 = h[(size_t)c2 * F8 + f];
        uint4 u3 = h[(size_t)c3 * F8 + f];
        float v0[8], v1[8], v2[8], v3[8];
        unpack8(u0, v0); unpack8(u1, v1); unpack8(u2, v2); unpack8(u3, v3);
        T(v0); T(v1); T(v2); T(v3);
        #pragma unroll
        for (int i = 0; i < 8; i++) {
            acc0[i] = fmaf(v0[i], w0, acc0[i]);
            acc1[i] = fmaf(v1[i], w1, acc1[i]);
            acc0[i] = fmaf(v2[i], w2, acc0[i]);
            acc1[i] = fmaf(v3[i], w3, acc1[i]);
        }
    }
    for (; e < end; e++) {
        int c = g_colidx[e];
        float w = g_w[e];
        float v[8];
        unpack8(h[(size_t)c * F8 + f], v);
        T(v);
        #pragma unroll
        for (int i = 0; i < 8; i++) acc0[i] = fmaf(v[i], w, acc0[i]);
    }

    float r[8];
    #pragma unroll
    for (int i = 0; i < 8; i++) r[i] = acc0[i] + acc1[i];
    out[(size_t)node * F8 + f] = pack8(r);
}

// Scalar fp32 aggregation for F=40 (layer 3 output)
template <int F, int NPB>
__global__ void agg_scalar_kernel(const float* __restrict__ h, float* __restrict__ out) {
    int local = threadIdx.x / F;
    int f = threadIdx.x % F;
    int node = blockIdx.x * NPB + local;
    if (node >= NNODES) return;

    int start = g_rowptr[node];
    int end = g_rowptr[node + 1];
    float di = g_dinv[node];
    float acc0 = di * di * h[(size_t)node * F + f];
    float acc1 = 0.f, acc2 = 0.f, acc3 = 0.f;

    int e = start;
    for (; e + 4 <= end; e += 4) {
        int c0 = g_colidx[e + 0], c1 = g_colidx[e + 1];
        int c2 = g_colidx[e + 2], c3 = g_colidx[e + 3];
        float w0 = g_w[e + 0], w1 = g_w[e + 1];
        float w2 = g_w[e + 2], w3 = g_w[e + 3];
        acc0 = fmaf(w0, h[(size_t)c0 * F + f], acc0);
        acc1 = fmaf(w1, h[(size_t)c1 * F + f], acc1);
        acc2 = fmaf(w2, h[(size_t)c2 * F + f], acc2);
        acc3 = fmaf(w3, h[(size_t)c3 * F + f], acc3);
    }
    for (; e < end; e++)
        acc0 = fmaf(g_w[e], h[(size_t)g_colidx[e] * F + f], acc0);

    out[(size_t)node * F + f] = (acc0 + acc1) + (acc2 + acc3);
}

// ---------------------------------------------------------------------------
// fp16 tensor-core GEMM with optional fusions:
//   BNIN : A is raw fp16; apply relu(a*scale[k]+shift[k]) while loading.
//   BNOUT: write C as raw fp16 AND accumulate per-column sum/sumsq into
//          g_sum/g_sumsq (BN statistics fused into epilogue).
//   PIPE : 2-stage cp.async double-buffered mainloop.
// 256 threads = 8 warps (4m x 2n); BK=32.
// ---------------------------------------------------------------------------
template <int BM, int BN, bool BNIN, bool BNOUT, bool PIPE>
__global__ __launch_bounds__(256) void gemm_f16_kernel(
    int M, int K, int Nreal,
    const __half* __restrict__ Ah, const __half* __restrict__ Wt, void* Cout)
{
    constexpr int BK = 32;
    constexpr int LDA = BK + 8;   // 40 halves = 80B (16B multiple)
    constexpr int LDB = BK + 8;
    constexpr int NSTG = PIPE ? 2 : 1;
    __shared__ __half As[NSTG * BM * LDA];
    __shared__ __half Bs[NSTG * BN * LDB];

    const int tid = threadIdx.x;
    const int lane = tid & 31;
    const int warp = tid >> 5;
    const int brow = blockIdx.x * BM;
    const int bcol = blockIdx.y * BN;

    constexpr int WTM = BM / 4;          // 32
    constexpr int WTN = BN / 2;          // 64 / 32
    constexpr int MT = WTM / 16;         // 2
    constexpr int NT = WTN / 8;          // 8 / 4
    const int warpRow = (warp & 3) * WTM;
    const int warpCol = (warp >> 2) * WTN;
    const int g = lane >> 2;
    const int t2 = (lane & 3) * 2;

    float c[MT][NT][4] = {};

    const int aRow = tid >> 2;           // 0..63
    const int aChunk = (tid & 3) * 8;    // halves (16B)

    // -------- tile loaders --------
    auto load_tile_async = [&](int k0, int stg) {
        __half* Asb = As + stg * BM * LDA;
        __half* Bsb = Bs + stg * BN * LDB;
        #pragma unroll
        for (int r = 0; r < BM; r += 64) {
            int gr = brow + aRow + r;
            int sz = (gr < M) ? 16 : 0;
            const __half* src = Ah + (size_t)(gr < M ? gr : 0) * K + k0 + aChunk;
            CP_ASYNC16(smem_u32(&Asb[(aRow + r) * LDA + aChunk]), src, sz);
        }
        #pragma unroll
        for (int n = 0; n < BN; n += 64) {
            const __half* src = Wt + (size_t)(bcol + aRow + n) * K + k0 + aChunk;
            CP_ASYNC16(smem_u32(&Bsb[(aRow + n) * LDB + aChunk]), src, 16);
        }
    };

    auto load_tile_bnin = [&](int k0) {
        float4 sc0 = *(const float4*)(g_scale + k0 + aChunk);
        float4 sc1 = *(const float4*)(g_scale + k0 + aChunk + 4);
        float4 sh0 = *(const float4*)(g_shift + k0 + aChunk);
        float4 sh1 = *(const float4*)(g_shift + k0 + aChunk + 4);
        float sc[8] = {sc0.x, sc0.y, sc0.z, sc0.w, sc1.x, sc1.y, sc1.z, sc1.w};
        float sh[8] = {sh0.x, sh0.y, sh0.z, sh0.w, sh1.x, sh1.y, sh1.z, sh1.w};
        #pragma unroll
        for (int r = 0; r < BM; r += 64) {
            int gr = brow + aRow + r;
            uint4 u = make_uint4(0, 0, 0, 0);
            if (gr < M) u = *(const uint4*)(Ah + (size_t)gr * K + k0 + aChunk);
            float f[8];
            unpack8(u, f);
            #pragma unroll
            for (int i = 0; i < 8; i++) f[i] = fmaxf(fmaf(f[i], sc[i], sh[i]), 0.f);
            *(uint4*)&As[(aRow + r) * LDA + aChunk] = pack8(f);
        }
        #pragma unroll
        for (int n = 0; n < BN; n += 64) {
            *(uint4*)&Bs[(aRow + n) * LDB + aChunk] =
                *(const uint4*)(Wt + (size_t)(bcol + aRow + n) * K + k0 + aChunk);
        }
    };

    auto compute = [&](int stg) {
        const __half* Asb = As + stg * BM * LDA;
        const __half* Bsb = Bs + stg * BN * LDB;
        #pragma unroll
        for (int kk = 0; kk < BK / 16; kk++) {
            uint32_t a[MT][4], b[NT][2];
            #pragma unroll
            for (int i = 0; i < MT; i++) {
                int r0 = warpRow + i * 16 + g;
                int cc = kk * 16 + t2;
                a[i][0] = *(const uint32_t*)&Asb[r0 * LDA + cc];
                a[i][1] = *(const uint32_t*)&Asb[(r0 + 8) * LDA + cc];
                a[i][2] = *(const uint32_t*)&Asb[r0 * LDA + cc + 8];
                a[i][3] = *(const uint32_t*)&Asb[(r0 + 8) * LDA + cc + 8];
            }
            #pragma unroll
            for (int j = 0; j < NT; j++) {
                int n = warpCol + j * 8 + g;
                int cc = kk * 16 + t2;
                b[j][0] = *(const uint32_t*)&Bsb[n * LDB + cc];
                b[j][1] = *(const uint32_t*)&Bsb[n * LDB + cc + 8];
            }
            #pragma unroll
            for (int i = 0; i < MT; i++)
                #pragma unroll
                for (int j = 0; j < NT; j++)
                    mma_f16(c[i][j], a[i], b[j]);
        }
    };

    // -------- mainloop --------
    if (PIPE) {
        int s = 0;
        load_tile_async(0, 0);
        CP_COMMIT();
        for (int k0 = 0; k0 < K; k0 += BK) {
            if (k0 + BK < K) {
                load_tile_async(k0 + BK, s ^ 1);
                CP_COMMIT();
                CP_WAIT(1);
            } else {
                CP_WAIT(0);
            }
            __syncthreads();
            compute(s);
            __syncthreads();
            s ^= 1;
        }
    } else {
        for (int k0 = 0; k0 < K; k0 += BK) {
            if (BNIN) load_tile_bnin(k0);
            __syncthreads();
            compute(0);
            __syncthreads();
        }
    }

    // -------- epilogue --------
    if (BNOUT) {
        __half* Ch = (__half*)Cout;
        float s[NT * 2] = {}, s2[NT * 2] = {};
        #pragma unroll
        for (int i = 0; i < MT; i++) {
            int r0 = brow + warpRow + i * 16 + g;
            bool v0 = r0 < M, v1 = (r0 + 8) < M;
            #pragma unroll
            for (int j = 0; j < NT; j++) {
                int col = bcol + warpCol + j * 8 + t2;
                if (v0) {
                    *(uint32_t*)(Ch + (size_t)r0 * Nreal + col) =
                        *(uint32_t*)&(__half2_raw)__floats2half2_rn(c[i][j][0], c[i][j][1]);
                    s[j * 2 + 0] += c[i][j][0];  s2[j * 2 + 0] += c[i][j][0] * c[i][j][0];
                    s[j * 2 + 1] += c[i][j][1];  s2[j * 2 + 1] += c[i][j][1] * c[i][j][1];
                }
                if (v1) {
                    *(uint32_t*)(Ch + (size_t)(r0 + 8) * Nreal + col) =
                        *(uint32_t*)&(__half2_raw)__floats2half2_rn(c[i][j][2], c[i][j][3]);
                    s[j * 2 + 0] += c[i][j][2];  s2[j * 2 + 0] += c[i][j][2] * c[i][j][2];
                    s[j * 2 + 1] += c[i][j][3];  s2[j * 2 + 1] += c[i][j][3] * c[i][j][3];
                }
            }
        }
        // reduce across g (lanes with same lane&3): xor 4, 8, 16
        #pragma unroll
        for (int off = 4; off <= 16; off <<= 1) {
            #pragma unroll
            for (int t = 0; t < NT * 2; t++) {
                s[t]  += __shfl_xor_sync(0xFFFFFFFFu, s[t],  off);
                s2[t] += __shfl_xor_sync(0xFFFFFFFFu, s2[t], off);
            }
        }
        // smem reduction across warps (reuse As)
        float* ssum  = reinterpret_cast<float*>(As);
        float* ssum2 = ssum + BN;
        __syncthreads();
        if (tid < 2 * BN) ssum[tid] = 0.f;
        __syncthreads();
        if (lane < 4) {
            #pragma unroll
            for (int j = 0; j < NT; j++) {
                #pragma unroll
                for (int hh = 0; hh < 2; hh++) {
                    int cl = warpCol + j * 8 + t2 + hh;
                    atomicAdd(&ssum[cl],  s[j * 2 + hh]);
                    atomicAdd(&ssum2[cl], s2[j * 2 + hh]);
                }
            }
        }
        __syncthreads();
        if (tid < BN) {
            atomicAdd(&g_sum[bcol + tid],   (double)ssum[tid]);
            atomicAdd(&g_sumsq[bcol + tid], (double)ssum2[tid]);
        }
    } else {
        float* C = (float*)Cout;
        #pragma unroll
        for (int i = 0; i < MT; i++) {
            int r0 = brow + warpRow + i * 16 + g;
            #pragma unroll
            for (int j = 0; j < NT; j++) {
                int col = bcol + warpCol + j * 8 + t2;
                if (col < Nreal) {
                    if (r0 < M)
                        *(float2*)(C + (size_t)r0 * Nreal + col) = make_float2(c[i][j][0], c[i][j][1]);
                    if (r0 + 8 < M)
                        *(float2*)(C + (size_t)(r0 + 8) * Nreal + col) = make_float2(c[i][j][2], c[i][j][3]);
                }
            }
        }
    }
}

// ---------------------------------------------------------------------------
// BN finalize + zero
// ---------------------------------------------------------------------------
__global__ void bn_zero_kernel() {
    int f = threadIdx.x;
    g_sum[f] = 0.0;
    g_sumsq[f] = 0.0;
}

__global__ void bn_finalize_kernel(const float* __restrict__ gamma,
                                   const float* __restrict__ beta) {
    int f = threadIdx.x;
    double mu = g_sum[f] / (double)NNODES;
    double var = g_sumsq[f] / (double)NNODES - mu * mu;
    float sc = gamma[f] * rsqrtf((float)var + BN_EPS);
    g_scale[f] = sc;
    g_shift[f] = beta[f] - (float)mu * sc;
}

// ---------------------------------------------------------------------------
// log_softmax over 40 classes (one warp per node), fused +b3
// ---------------------------------------------------------------------------
__global__ void logsoftmax_kernel(const float* __restrict__ in,
                                  const float* __restrict__ b3,
                                  float* __restrict__ out) {
    int warp = (blockIdx.x * blockDim.x + threadIdx.x) >> 5;
    int lane = threadIdx.x & 31;
    if (warp >= NNODES) return;
    const float* r = in + (size_t)warp * 40;
    float v0 = r[lane] + b3[lane];
    bool has2 = (lane + 32) < 40;
    float v1 = has2 ? (r[lane + 32] + b3[lane + 32]) : -INFINITY;

    float m = fmaxf(v0, v1);
    #pragma unroll
    for (int o = 16; o > 0; o >>= 1) m = fmaxf(m, __shfl_xor_sync(0xFFFFFFFFu, m, o));

    float s = expf(v0 - m) + (has2 ? expf(v1 - m) : 0.f);
    #pragma unroll
    for (int o = 16; o > 0; o >>= 1) s += __shfl_xor_sync(0xFFFFFFFFu, s, o);

    float lse = m + logf(s);
    out[(size_t)warp * 40 + lane] = v0 - lse;
    if (has2) out[(size_t)warp * 40 + lane + 32] = v1 - lse;
}

// ---------------------------------------------------------------------------
// Launch
// ---------------------------------------------------------------------------
extern "C" void kernel_launch(void* const* d_in, const int* in_sizes, int n_in,
                              void* d_out, int out_size) {
    const float* x      = (const float*)d_in[0];
    const int*   ei     = (const int*)d_in[1];
    const float* W1     = (const float*)d_in[2];
    const float* gamma1 = (const float*)d_in[4];
    const float* beta1  = (const float*)d_in[5];
    const float* W2     = (const float*)d_in[6];
    const float* gamma2 = (const float*)d_in[8];
    const float* beta2  = (const float*)d_in[9];
    const float* W3     = (const float*)d_in[10];
    const float* b3     = (const float*)d_in[11];
    float* out = (float*)d_out;

    const int* row = ei;
    const int* col = ei + NEDGES;

    float *buf3, *buf4;
    __half *xh, *a1h, *h1h, *a2h, *h2h, *wt1, *wt2, *wt3;
    cudaGetSymbolAddress((void**)&buf3, g_buf3);
    cudaGetSymbolAddress((void**)&buf4, g_buf4);
    cudaGetSymbolAddress((void**)&xh,  g_xh);
    cudaGetSymbolAddress((void**)&a1h, g_a1h);
    cudaGetSymbolAddress((void**)&h1h, g_h1h);
    cudaGetSymbolAddress((void**)&a2h, g_a2h);
    cudaGetSymbolAddress((void**)&h2h, g_h2h);
    cudaGetSymbolAddress((void**)&wt1, g_wt1);
    cudaGetSymbolAddress((void**)&wt2, g_wt2);
    cudaGetSymbolAddress((void**)&wt3, g_wt3);

    const int EB = (NEDGES + 255) / 256;
    const int NB = (NNODES + 255) / 256;
    const int GROWS = (NNODES + 127) / 128;   // 1563

    // ---- Prep ----
    convert_w_kernel<<<(256 * 128 + 255) / 256, 256>>>(W1, wt1, 128, 256, 256);
    convert_w_kernel<<<(256 * 256 + 255) / 256, 256>>>(W2, wt2, 256, 256, 256);
    convert_w_kernel<<<(64 * 256 + 255) / 256, 256>>>(W3, wt3, 256, 40, 64);
    {
        size_t n4 = (size_t)NNODES * 128 / 4;
        f32_to_f16_kernel<<<(int)((n4 + 255) / 256), 256>>>(
            (const float4*)x, (uint2*)xh, n4);
    }

    // ---- CSR build ----
    zero_counts_kernel<<<NB, 256>>>();
    count_kernel<<<EB, 256>>>(row);
    dinv_kernel<<<NB, 256>>>();
    scan_block_sums_kernel<<<SCAN_BLOCKS, 1024>>>();
    scan_bsums_kernel<<<1, 256>>>();
    scan_write_kernel<<<SCAN_BLOCKS, 1024>>>();
    fill_kernel<<<EB, 256>>>(row, col);

    // ---- Layer 1: agg(xh) -> GEMM(128->256, fp16 out + fused BN stats) ----
    bn_zero_kernel<<<1, 256>>>();
    agg_f16_kernel<16, 16, false><<<NNODES / 16, 256>>>((const uint4*)xh, (uint4*)a1h);
    gemm_f16_kernel<128, 128, false, true, true><<<dim3(GROWS, 2), 256>>>(
        NNODES, 128, 256, a1h, wt1, h1h);
    bn_finalize_kernel<<<1, 256>>>(gamma1, beta1);

    // ---- Layer 2: agg(BNReLU on-the-fly) -> GEMM(256->256, fused stats) ----
    agg_f16_kernel<32, 8, true><<<NNODES / 8, 256>>>((const uint4*)h1h, (uint4*)a2h);
    bn_zero_kernel<<<1, 256>>>();
    gemm_f16_kernel<128, 128, false, true, true><<<dim3(GROWS, 2), 256>>>(
        NNODES, 256, 256, a2h, wt2, h2h);
    bn_finalize_kernel<<<1, 256>>>(gamma2, beta2);

    // ---- Layer 3: GEMM(BNReLU fused A-load, 256->40) -> agg -> logsoftmax ----
    gemm_f16_kernel<128, 64, true, false, false><<<dim3(GROWS, 1), 256>>>(
        NNODES, 256, 40, h2h, wt3, buf3);
    agg_scalar_kernel<40, 6><<<(NNODES + 5) / 6, 240>>>(buf3, buf4);
    logsoftmax_kernel<<<(NNODES + 7) / 8, 256>>>(buf4, b3, out);
}